// round 5
// baseline (speedup 1.0000x reference)
#include <cuda_runtime.h>
#include <cuda_bf16.h>

#define N_NODES 50000
#define E_EDGES 800000
#define H_DIM   64
#define GAMMA   0.2f

#define SCAN_CHUNK 1024
#define SCAN_NBLK  ((N_NODES + SCAN_CHUNK - 1) / SCAN_CHUNK)   // 49

// ---------------- device scratch (static, allocation-free) ----------------
__device__ float    g_vsrc[H_DIM];
__device__ float    g_vdst[H_DIM];
__device__ float    g_s0[N_NODES];        // scores for layer-0 input (emb)
__device__ float    g_d0[N_NODES];
__device__ float    g_s1[N_NODES];        // scores for layer-1 input (h after L0)
__device__ float    g_d1[N_NODES];
__device__ unsigned g_cnt[N_NODES];
__device__ unsigned g_rowptr[N_NODES + 1];
__device__ unsigned g_cursor[N_NODES];
__device__ unsigned g_blksum[SCAN_NBLK];
__device__ unsigned g_blkoff[SCAN_NBLK];
__device__ int      g_srcs[E_EDGES];      // src id, grouped by dst (CSR)
__device__ float    g_ex[E_EDGES];        // last-layer exp(e), CSR order
__device__ float    g_dinv[N_NODES];      // last-layer 1/denom
__device__ float    g_h[N_NODES * H_DIM];
__device__ float    g_sumA;
__device__ float    g_sumB;

// ---------------- kernels ----------------

// v_src = W^T a_src, v_dst = W^T a_dst ; zero loss accumulators
__global__ void k_prep(const float* __restrict__ W, const float* __restrict__ attn) {
    int t = threadIdx.x;  // 128 threads
    if (t == 0) { g_sumA = 0.f; g_sumB = 0.f; }
    if (t < H_DIM) {
        float acc = 0.f;
        #pragma unroll 8
        for (int r = 0; r < H_DIM; r++) acc += attn[r] * W[r * H_DIM + t];
        g_vsrc[t] = acc;
    } else {
        int c = t - H_DIM;
        float acc = 0.f;
        #pragma unroll 8
        for (int r = 0; r < H_DIM; r++) acc += attn[H_DIM + r] * W[r * H_DIM + c];
        g_vdst[c] = acc;
    }
}

__global__ void k_hist(const int* __restrict__ dst) {
    int i = blockIdx.x * blockDim.x + threadIdx.x;
    if (i < E_EDGES) atomicAdd(&g_cnt[dst[i]], 1u);
}

// step 1: per-block exclusive scan of g_cnt -> g_rowptr (block-local), totals -> g_blksum
__global__ void k_scan1() {
    __shared__ unsigned warp_sums[32];
    int t = threadIdx.x, lane = t & 31, wid = t >> 5;
    int idx = blockIdx.x * SCAN_CHUNK + t;

    unsigned orig = (idx < N_NODES) ? g_cnt[idx] : 0u;
    unsigned v = orig;
    #pragma unroll
    for (int o = 1; o < 32; o <<= 1) {
        unsigned u = __shfl_up_sync(0xffffffffu, v, o);
        if (lane >= o) v += u;
    }
    if (lane == 31) warp_sums[wid] = v;
    __syncthreads();
    if (wid == 0) {
        unsigned w = warp_sums[lane];
        #pragma unroll
        for (int o = 1; o < 32; o <<= 1) {
            unsigned u = __shfl_up_sync(0xffffffffu, w, o);
            if (lane >= o) w += u;
        }
        warp_sums[lane] = w;
    }
    __syncthreads();
    unsigned pre = (wid > 0) ? warp_sums[wid - 1] : 0u;
    if (idx < N_NODES) g_rowptr[idx] = pre + v - orig;   // block-local exclusive
    if (t == SCAN_CHUNK - 1) g_blksum[blockIdx.x] = warp_sums[31];
}

// step 2: one warp scans SCAN_NBLK (=49) block totals -> g_blkoff, total -> rowptr[N]
__global__ void k_scan2() {
    int lane = threadIdx.x;  // 32 threads
    unsigned o0 = (lane < SCAN_NBLK) ? g_blksum[lane] : 0u;
    unsigned o1 = (32 + lane < SCAN_NBLK) ? g_blksum[32 + lane] : 0u;
    unsigned v0 = o0, v1 = o1;
    #pragma unroll
    for (int o = 1; o < 32; o <<= 1) {
        unsigned u0 = __shfl_up_sync(0xffffffffu, v0, o);
        unsigned u1 = __shfl_up_sync(0xffffffffu, v1, o);
        if (lane >= o) { v0 += u0; v1 += u1; }
    }
    unsigned tot0 = __shfl_sync(0xffffffffu, v0, 31);
    v1 += tot0;
    unsigned total = __shfl_sync(0xffffffffu, v1, 31);
    if (lane < SCAN_NBLK) g_blkoff[lane] = v0 - o0;
    if (32 + lane < SCAN_NBLK) g_blkoff[32 + lane] = v1 - o1;
    if (lane == 0) g_rowptr[N_NODES] = total;
}

// step 3: add block offsets; mirror into g_cursor
__global__ void k_scan3() {
    int i = blockIdx.x * blockDim.x + threadIdx.x;
    if (i >= N_NODES) return;
    unsigned r = g_rowptr[i] + g_blkoff[i / SCAN_CHUNK];
    g_rowptr[i] = r;
    g_cursor[i] = r;
}

__global__ void k_scatter(const int* __restrict__ src, const int* __restrict__ dst) {
    int i = blockIdx.x * blockDim.x + threadIdx.x;
    if (i >= E_EDGES) return;
    unsigned pos = atomicAdd(&g_cursor[dst[i]], 1u);
    g_srcs[pos] = src[i];
}

// per node: s = h.v_src, d = h.v_dst  (8 threads per node) -> g_s0/g_d0
__global__ void k_node_scores(const float* __restrict__ h) {
    int gid  = blockIdx.x * blockDim.x + threadIdx.x;
    int node = gid >> 3;
    int part = gid & 7;
    if (node >= N_NODES) return;   // whole-warp aligned exits

    const float4* hp = (const float4*)(h + (size_t)node * H_DIM);
    const float4* vs = (const float4*)g_vsrc;
    const float4* vd = (const float4*)g_vdst;
    float4 a = hp[part * 2], b = hp[part * 2 + 1];
    float4 v0 = vs[part * 2], v1 = vs[part * 2 + 1];
    float4 w0 = vd[part * 2], w1 = vd[part * 2 + 1];

    float s = a.x * v0.x + a.y * v0.y + a.z * v0.z + a.w * v0.w
            + b.x * v1.x + b.y * v1.y + b.z * v1.z + b.w * v1.w;
    float d = a.x * w0.x + a.y * w0.y + a.z * w0.z + a.w * w0.w
            + b.x * w1.x + b.y * w1.y + b.z * w1.z + b.w * w1.w;

    #pragma unroll
    for (int off = 4; off; off >>= 1) {
        s += __shfl_xor_sync(0xffffffffu, s, off);
        d += __shfl_xor_sync(0xffffffffu, d, off);
    }
    if (part == 0) { g_s0[node] = s; g_d0[node] = d; }
}

// fused per-node layer, SINGLE PASS (no segment max: e ~ N(0,1), exp safe).
// 16 threads per node; no atomics in the hot path.
// WSCORES: compute next-layer scores from the fresh h row (into g_s1/g_d1).
// FINAL:   store per-edge ex + 1/denom for the loss, accumulate loss_a.
template <int FINAL, int WSCORES>
__global__ void k_layer(const float* __restrict__ h_in,
                        const float* __restrict__ emb,
                        float* __restrict__ h_out,
                        const float* __restrict__ s_in,
                        const float* __restrict__ d_in) {
    int gid  = blockIdx.x * blockDim.x + threadIdx.x;   // exact grid: N*16
    int node = gid >> 4;
    int part = gid & 15;

    unsigned beg = g_rowptr[node], end = g_rowptr[node + 1];
    float dloc = d_in[node];

    float4 acc = make_float4(0.f, 0.f, 0.f, 0.f);
    float den = 0.f;
    for (unsigned j = beg; j < end; j++) {
        int sj = g_srcs[j];                    // uniform within group -> broadcast
        float e = s_in[sj] + dloc;             // L1/L2-resident scalar
        e = e > 0.f ? e : GAMMA * e;
        float ex = __expf(e);
        den += ex;
        float4 hv = *(const float4*)(h_in + (size_t)sj * H_DIM + part * 4);
        acc.x += ex * hv.x; acc.y += ex * hv.y;
        acc.z += ex * hv.z; acc.w += ex * hv.w;
        if (FINAL && part == 0) g_ex[j] = ex;
    }
    float inv = 1.f / fmaxf(den, 1e-16f);
    float4 eb = *(const float4*)(emb + (size_t)node * H_DIM + part * 4);
    float4 hv = make_float4(0.5f * (eb.x + acc.x * inv), 0.5f * (eb.y + acc.y * inv),
                            0.5f * (eb.z + acc.z * inv), 0.5f * (eb.w + acc.w * inv));
    *(float4*)(h_out + (size_t)node * H_DIM + part * 4) = hv;

    // ----- post-loop: all 32 lanes reconverged; full-mask shuffles safe -----
    if (WSCORES) {
        float4 v0 = ((const float4*)g_vsrc)[part];
        float4 w0 = ((const float4*)g_vdst)[part];
        float sp = hv.x * v0.x + hv.y * v0.y + hv.z * v0.z + hv.w * v0.w;
        float dp = hv.x * w0.x + hv.y * w0.y + hv.z * w0.z + hv.w * w0.w;
        #pragma unroll
        for (int off = 8; off; off >>= 1) {
            sp += __shfl_xor_sync(0xffffffffu, sp, off);
            dp += __shfl_xor_sync(0xffffffffu, dp, off);
        }
        if (part == 0) { g_s1[node] = sp; g_d1[node] = dp; }
    }

    if (FINAL) {
        if (part == 0) g_dinv[node] = inv;
        float dx = hv.x - eb.x, dy = hv.y - eb.y, dz = hv.z - eb.z, dw = hv.w - eb.w;
        float sq = dx * dx + dy * dy + dz * dz + dw * dw;
        #pragma unroll
        for (int off = 16; off; off >>= 1) sq += __shfl_xor_sync(0xffffffffu, sq, off);
        __shared__ float sm[8];
        if ((threadIdx.x & 31) == 0) sm[threadIdx.x >> 5] = sq;
        __syncthreads();
        if (threadIdx.x < 8) {
            float v = sm[threadIdx.x];
            #pragma unroll
            for (int o = 4; o; o >>= 1) v += __shfl_xor_sync(0xffu, v, o);
            if (threadIdx.x == 0) atomicAdd(&g_sumA, v);
        }
    }
}

// loss_b, lane-per-edge: h[dst] row staged in smem (broadcast reads);
// each lane owns whole edges -> zero in-loop shuffles, MLP=16 on the gather.
__global__ void k_loss(const float* __restrict__ h) {
    int gid  = blockIdx.x * blockDim.x + threadIdx.x;   // exact grid: N*16
    int node = gid >> 4;
    int part = gid & 15;
    int grp  = threadIdx.x >> 4;                        // 0..15 in block of 256

    __shared__ float shd[16][H_DIM + 4];                // +4 pad: distinct banks per group

    unsigned beg = g_rowptr[node], end = g_rowptr[node + 1];
    float4 hd4 = *(const float4*)(h + (size_t)node * H_DIM + part * 4);
    *(float4*)&shd[grp][part * 4] = hd4;
    __syncwarp();                                        // converged here
    float dinv = g_dinv[node];

    float sum = 0.f;
    for (unsigned j = beg + part; j < end; j += 16) {
        int sj = g_srcs[j];
        const float4* hs = (const float4*)(h + (size_t)sj * H_DIM);
        float sq = 0.f;
        #pragma unroll
        for (int k = 0; k < 16; k++) {
            float4 a = hs[k];
            float4 b = *(const float4*)&shd[grp][k * 4];
            float dx = b.x - a.x, dy = b.y - a.y, dz = b.z - a.z, dw = b.w - a.w;
            sq += dx * dx + dy * dy + dz * dz + dw * dw;
        }
        sum += g_ex[j] * sqrtf(sq + 1e-12f);
    }
    sum *= dinv;   // per-lane partial of the GLOBAL loss_b sum

    // post-loop reconvergence: full-warp + block reduce, one atomic per block
    #pragma unroll
    for (int off = 16; off; off >>= 1) sum += __shfl_xor_sync(0xffffffffu, sum, off);
    __shared__ float sm[8];
    if ((threadIdx.x & 31) == 0) sm[threadIdx.x >> 5] = sum;
    __syncthreads();
    if (threadIdx.x < 8) {
        float v = sm[threadIdx.x];
        #pragma unroll
        for (int o = 4; o; o >>= 1) v += __shfl_xor_sync(0xffu, v, o);
        if (threadIdx.x == 0) atomicAdd(&g_sumB, v);
    }
}

__global__ void k_finalize(float* __restrict__ out) {
    out[N_NODES * H_DIM] = 0.5f * (g_sumA + g_sumB) / (float)N_NODES;
}

// ---------------- launch ----------------
extern "C" void kernel_launch(void* const* d_in, const int* in_sizes, int n_in,
                              void* d_out, int out_size) {
    const float* emb  = (const float*)d_in[0];   // [N, H]
    const float* W    = (const float*)d_in[1];   // [H, H]
    const float* attn = (const float*)d_in[2];   // [1, 2H]
    const int*   src  = (const int*)d_in[3];     // [E]
    const int*   dst  = (const int*)d_in[4];     // [E]
    float* out = (float*)d_out;                  // [N*H + 1]

    float *h_buf = nullptr, *cnt_ptr = nullptr;
    float *s0 = nullptr, *d0 = nullptr, *s1 = nullptr, *d1 = nullptr;
    cudaGetSymbolAddress((void**)&h_buf, g_h);
    cudaGetSymbolAddress((void**)&cnt_ptr, g_cnt);
    cudaGetSymbolAddress((void**)&s0, g_s0);
    cudaGetSymbolAddress((void**)&d0, g_d0);
    cudaGetSymbolAddress((void**)&s1, g_s1);
    cudaGetSymbolAddress((void**)&d1, g_d1);

    const int NB_NODE1  = (N_NODES + 255) / 256;       // 196
    const int NB_EDGE1  = (E_EDGES + 255) / 256;       // 3125
    const int NB_SCORE  = (N_NODES * 8 + 255) / 256;   // 1563
    const int NB_NODE16 = (N_NODES * 16) / 256;        // 3125 (exact)

    k_prep<<<1, 128>>>(W, attn);

    // ---- CSR build (dst-grouped), hierarchical scan ----
    cudaMemsetAsync(cnt_ptr, 0, N_NODES * sizeof(unsigned));
    k_hist<<<NB_EDGE1, 256>>>(dst);
    k_scan1<<<SCAN_NBLK, SCAN_CHUNK>>>();
    k_scan2<<<1, 32>>>();
    k_scan3<<<NB_NODE1, 256>>>();
    k_scatter<<<NB_EDGE1, 256>>>(src, dst);

    // ---- scores for layer 0 input ----
    k_node_scores<<<NB_SCORE, 256>>>(emb);

    // ---- layer 0 (emb -> g_h), fused next-layer scores ----
    k_layer<0, 1><<<NB_NODE16, 256>>>(emb, emb, h_buf, s0, d0);

    // ---- layer 1 (g_h -> out), final: store ex/dinv, loss_a ----
    k_layer<1, 0><<<NB_NODE16, 256>>>(h_buf, emb, out, s1, d1);

    // ---- loss_b ----
    k_loss<<<NB_NODE16, 256>>>(out);
    k_finalize<<<1, 1>>>(out);
}

// round 6
// speedup vs baseline: 1.2496x; 1.2496x over previous
#include <cuda_runtime.h>
#include <cuda_bf16.h>

#define N_NODES 50000
#define E_EDGES 800000
#define H_DIM   64
#define GAMMA   0.2f

#define SCAN_CHUNK 1024
#define SCAN_NBLK  ((N_NODES + SCAN_CHUNK - 1) / SCAN_CHUNK)   // 49

// ---------------- device scratch (static, allocation-free) ----------------
__device__ float    g_vsrc[H_DIM];
__device__ float    g_vdst[H_DIM];
__device__ float    g_s0[N_NODES];        // scores for layer-0 input (emb)
__device__ float    g_d0[N_NODES];
__device__ float    g_s1[N_NODES];        // scores for layer-1 input (h after L0)
__device__ float    g_d1[N_NODES];
__device__ unsigned g_cnt[N_NODES];
__device__ unsigned g_rowptr[N_NODES + 1];
__device__ unsigned g_cursor[N_NODES];
__device__ unsigned g_blksum[SCAN_NBLK];
__device__ unsigned g_blkoff[SCAN_NBLK];
__device__ int      g_srcs[E_EDGES];      // src id, grouped by dst (CSR)
__device__ float    g_ex[E_EDGES];        // last-layer exp(e), CSR order
__device__ float    g_dinv[N_NODES];      // last-layer 1/denom
__device__ float    g_h[N_NODES * H_DIM];
__device__ float    g_sumA;
__device__ float    g_sumB;

// ---------------- kernels ----------------

// v_src = W^T a_src, v_dst = W^T a_dst ; zero loss accumulators
__global__ void k_prep(const float* __restrict__ W, const float* __restrict__ attn) {
    int t = threadIdx.x;  // 128 threads
    if (t == 0) { g_sumA = 0.f; g_sumB = 0.f; }
    if (t < H_DIM) {
        float acc = 0.f;
        #pragma unroll 8
        for (int r = 0; r < H_DIM; r++) acc += attn[r] * W[r * H_DIM + t];
        g_vsrc[t] = acc;
    } else {
        int c = t - H_DIM;
        float acc = 0.f;
        #pragma unroll 8
        for (int r = 0; r < H_DIM; r++) acc += attn[H_DIM + r] * W[r * H_DIM + c];
        g_vdst[c] = acc;
    }
}

__global__ void k_hist(const int* __restrict__ dst) {
    int i = blockIdx.x * blockDim.x + threadIdx.x;
    if (i < E_EDGES) atomicAdd(&g_cnt[dst[i]], 1u);
}

// step 1: per-block exclusive scan of g_cnt -> g_rowptr (block-local), totals -> g_blksum
__global__ void k_scan1() {
    __shared__ unsigned warp_sums[32];
    int t = threadIdx.x, lane = t & 31, wid = t >> 5;
    int idx = blockIdx.x * SCAN_CHUNK + t;

    unsigned orig = (idx < N_NODES) ? g_cnt[idx] : 0u;
    unsigned v = orig;
    #pragma unroll
    for (int o = 1; o < 32; o <<= 1) {
        unsigned u = __shfl_up_sync(0xffffffffu, v, o);
        if (lane >= o) v += u;
    }
    if (lane == 31) warp_sums[wid] = v;
    __syncthreads();
    if (wid == 0) {
        unsigned w = warp_sums[lane];
        #pragma unroll
        for (int o = 1; o < 32; o <<= 1) {
            unsigned u = __shfl_up_sync(0xffffffffu, w, o);
            if (lane >= o) w += u;
        }
        warp_sums[lane] = w;
    }
    __syncthreads();
    unsigned pre = (wid > 0) ? warp_sums[wid - 1] : 0u;
    if (idx < N_NODES) g_rowptr[idx] = pre + v - orig;   // block-local exclusive
    if (t == SCAN_CHUNK - 1) g_blksum[blockIdx.x] = warp_sums[31];
}

// step 2: one warp scans SCAN_NBLK (=49) block totals -> g_blkoff, total -> rowptr[N]
__global__ void k_scan2() {
    int lane = threadIdx.x;  // 32 threads
    unsigned o0 = (lane < SCAN_NBLK) ? g_blksum[lane] : 0u;
    unsigned o1 = (32 + lane < SCAN_NBLK) ? g_blksum[32 + lane] : 0u;
    unsigned v0 = o0, v1 = o1;
    #pragma unroll
    for (int o = 1; o < 32; o <<= 1) {
        unsigned u0 = __shfl_up_sync(0xffffffffu, v0, o);
        unsigned u1 = __shfl_up_sync(0xffffffffu, v1, o);
        if (lane >= o) { v0 += u0; v1 += u1; }
    }
    unsigned tot0 = __shfl_sync(0xffffffffu, v0, 31);
    v1 += tot0;
    unsigned total = __shfl_sync(0xffffffffu, v1, 31);
    if (lane < SCAN_NBLK) g_blkoff[lane] = v0 - o0;
    if (32 + lane < SCAN_NBLK) g_blkoff[32 + lane] = v1 - o1;
    if (lane == 0) g_rowptr[N_NODES] = total;
}

// step 3: add block offsets; mirror into g_cursor
__global__ void k_scan3() {
    int i = blockIdx.x * blockDim.x + threadIdx.x;
    if (i >= N_NODES) return;
    unsigned r = g_rowptr[i] + g_blkoff[i / SCAN_CHUNK];
    g_rowptr[i] = r;
    g_cursor[i] = r;
}

__global__ void k_scatter(const int* __restrict__ src, const int* __restrict__ dst) {
    int i = blockIdx.x * blockDim.x + threadIdx.x;
    if (i >= E_EDGES) return;
    unsigned pos = atomicAdd(&g_cursor[dst[i]], 1u);
    g_srcs[pos] = src[i];
}

// per node: s = h.v_src, d = h.v_dst  (8 threads per node) -> g_s0/g_d0
__global__ void k_node_scores(const float* __restrict__ h) {
    int gid  = blockIdx.x * blockDim.x + threadIdx.x;
    int node = gid >> 3;
    int part = gid & 7;
    if (node >= N_NODES) return;   // whole-warp aligned exits

    const float4* hp = (const float4*)(h + (size_t)node * H_DIM);
    const float4* vs = (const float4*)g_vsrc;
    const float4* vd = (const float4*)g_vdst;
    float4 a = hp[part * 2], b = hp[part * 2 + 1];
    float4 v0 = vs[part * 2], v1 = vs[part * 2 + 1];
    float4 w0 = vd[part * 2], w1 = vd[part * 2 + 1];

    float s = a.x * v0.x + a.y * v0.y + a.z * v0.z + a.w * v0.w
            + b.x * v1.x + b.y * v1.y + b.z * v1.z + b.w * v1.w;
    float d = a.x * w0.x + a.y * w0.y + a.z * w0.z + a.w * w0.w
            + b.x * w1.x + b.y * w1.y + b.z * w1.z + b.w * w1.w;

    #pragma unroll
    for (int off = 4; off; off >>= 1) {
        s += __shfl_xor_sync(0xffffffffu, s, off);
        d += __shfl_xor_sync(0xffffffffu, d, off);
    }
    if (part == 0) { g_s0[node] = s; g_d0[node] = d; }
}

// fused per-node layer, SINGLE PASS (no segment max: e ~ N(0,1), exp safe;
// softmax ratio is shift-invariant so result is identical).
// 16 threads per node; coalesced row reads; no atomics in the hot path.
// WSCORES: compute next-layer scores from the fresh h row (into g_s1/g_d1).
// FINAL:   store per-edge ex + 1/denom for the loss, accumulate loss_a.
template <int FINAL, int WSCORES>
__global__ void k_layer(const float* __restrict__ h_in,
                        const float* __restrict__ emb,
                        float* __restrict__ h_out,
                        const float* __restrict__ s_in,
                        const float* __restrict__ d_in) {
    int gid  = blockIdx.x * blockDim.x + threadIdx.x;   // exact grid: N*16
    int node = gid >> 4;
    int part = gid & 15;

    unsigned beg = g_rowptr[node], end = g_rowptr[node + 1];
    float dloc = d_in[node];

    float4 acc = make_float4(0.f, 0.f, 0.f, 0.f);
    float den = 0.f;
    for (unsigned j = beg; j < end; j++) {
        int sj = g_srcs[j];                    // uniform within group -> broadcast
        float e = s_in[sj] + dloc;             // L1/L2-resident scalar, broadcast
        e = e > 0.f ? e : GAMMA * e;
        float ex = __expf(e);
        den += ex;
        float4 hv = *(const float4*)(h_in + (size_t)sj * H_DIM + part * 4);
        acc.x += ex * hv.x; acc.y += ex * hv.y;
        acc.z += ex * hv.z; acc.w += ex * hv.w;
        if (FINAL && part == 0) g_ex[j] = ex;
    }
    float inv = 1.f / fmaxf(den, 1e-16f);
    float4 eb = *(const float4*)(emb + (size_t)node * H_DIM + part * 4);
    float4 hv = make_float4(0.5f * (eb.x + acc.x * inv), 0.5f * (eb.y + acc.y * inv),
                            0.5f * (eb.z + acc.z * inv), 0.5f * (eb.w + acc.w * inv));
    *(float4*)(h_out + (size_t)node * H_DIM + part * 4) = hv;

    // ----- post-loop: all 32 lanes reconverged; full-mask shuffles safe -----
    if (WSCORES) {
        float4 v0 = ((const float4*)g_vsrc)[part];
        float4 w0 = ((const float4*)g_vdst)[part];
        float sp = hv.x * v0.x + hv.y * v0.y + hv.z * v0.z + hv.w * v0.w;
        float dp = hv.x * w0.x + hv.y * w0.y + hv.z * w0.z + hv.w * w0.w;
        #pragma unroll
        for (int off = 8; off; off >>= 1) {
            sp += __shfl_xor_sync(0xffffffffu, sp, off);
            dp += __shfl_xor_sync(0xffffffffu, dp, off);
        }
        if (part == 0) { g_s1[node] = sp; g_d1[node] = dp; }
    }

    if (FINAL) {
        if (part == 0) g_dinv[node] = inv;
        float dx = hv.x - eb.x, dy = hv.y - eb.y, dz = hv.z - eb.z, dw = hv.w - eb.w;
        float sq = dx * dx + dy * dy + dz * dz + dw * dw;
        #pragma unroll
        for (int off = 16; off; off >>= 1) sq += __shfl_xor_sync(0xffffffffu, sq, off);
        __shared__ float sm[8];
        if ((threadIdx.x & 31) == 0) sm[threadIdx.x >> 5] = sq;
        __syncthreads();
        if (threadIdx.x < 8) {
            float v = sm[threadIdx.x];
            #pragma unroll
            for (int o = 4; o; o >>= 1) v += __shfl_xor_sync(0xffu, v, o);
            if (threadIdx.x == 0) atomicAdd(&g_sumA, v);
        }
    }
}

// loss_b, lane-per-part (COALESCED: 16 lanes read one contiguous row per edge).
// In-loop shuffles use the 16-lane group mask (legal under divergent trip counts);
// 4 shuffles/edge are ALU-cheap vs the uncoalesced-gather alternative.
__global__ void k_loss(const float* __restrict__ h) {
    int gid  = blockIdx.x * blockDim.x + threadIdx.x;   // exact grid: N*16
    int node = gid >> 4;
    int part = gid & 15;
    unsigned gmask = 0xFFFFu << (threadIdx.x & 16);

    unsigned beg = g_rowptr[node], end = g_rowptr[node + 1];
    float4 hd = *(const float4*)(h + (size_t)node * H_DIM + part * 4);
    float dinv = g_dinv[node];

    float sum = 0.f;
    for (unsigned j = beg; j < end; j++) {
        int sj = g_srcs[j];
        float4 hs = *(const float4*)(h + (size_t)sj * H_DIM + part * 4);
        float dx = hd.x - hs.x, dy = hd.y - hs.y, dz = hd.z - hs.z, dw = hd.w - hs.w;
        float sq = dx * dx + dy * dy + dz * dz + dw * dw;
        #pragma unroll
        for (int off = 8; off; off >>= 1)
            sq += __shfl_xor_sync(gmask, sq, off);      // group-local
        sum += g_ex[j] * sqrtf(sq + 1e-12f);
    }
    sum = (part == 0) ? sum * dinv : 0.f;   // one copy per node
    // converged below loop: full-warp reduction safe
    #pragma unroll
    for (int off = 16; off; off >>= 1) sum += __shfl_xor_sync(0xffffffffu, sum, off);
    __shared__ float sm[8];
    if ((threadIdx.x & 31) == 0) sm[threadIdx.x >> 5] = sum;
    __syncthreads();
    if (threadIdx.x < 8) {
        float v = sm[threadIdx.x];
        #pragma unroll
        for (int o = 4; o; o >>= 1) v += __shfl_xor_sync(0xffu, v, o);
        if (threadIdx.x == 0) atomicAdd(&g_sumB, v);
    }
}

__global__ void k_finalize(float* __restrict__ out) {
    out[N_NODES * H_DIM] = 0.5f * (g_sumA + g_sumB) / (float)N_NODES;
}

// ---------------- launch ----------------
extern "C" void kernel_launch(void* const* d_in, const int* in_sizes, int n_in,
                              void* d_out, int out_size) {
    const float* emb  = (const float*)d_in[0];   // [N, H]
    const float* W    = (const float*)d_in[1];   // [H, H]
    const float* attn = (const float*)d_in[2];   // [1, 2H]
    const int*   src  = (const int*)d_in[3];     // [E]
    const int*   dst  = (const int*)d_in[4];     // [E]
    float* out = (float*)d_out;                  // [N*H + 1]

    float *h_buf = nullptr, *cnt_ptr = nullptr;
    float *s0 = nullptr, *d0 = nullptr, *s1 = nullptr, *d1 = nullptr;
    cudaGetSymbolAddress((void**)&h_buf, g_h);
    cudaGetSymbolAddress((void**)&cnt_ptr, g_cnt);
    cudaGetSymbolAddress((void**)&s0, g_s0);
    cudaGetSymbolAddress((void**)&d0, g_d0);
    cudaGetSymbolAddress((void**)&s1, g_s1);
    cudaGetSymbolAddress((void**)&d1, g_d1);

    const int NB_NODE1  = (N_NODES + 255) / 256;       // 196
    const int NB_EDGE1  = (E_EDGES + 255) / 256;       // 3125
    const int NB_SCORE  = (N_NODES * 8 + 255) / 256;   // 1563
    const int NB_NODE16 = (N_NODES * 16) / 256;        // 3125 (exact)

    k_prep<<<1, 128>>>(W, attn);

    // ---- CSR build (dst-grouped), hierarchical scan ----
    cudaMemsetAsync(cnt_ptr, 0, N_NODES * sizeof(unsigned));
    k_hist<<<NB_EDGE1, 256>>>(dst);
    k_scan1<<<SCAN_NBLK, SCAN_CHUNK>>>();
    k_scan2<<<1, 32>>>();
    k_scan3<<<NB_NODE1, 256>>>();
    k_scatter<<<NB_EDGE1, 256>>>(src, dst);

    // ---- scores for layer 0 input ----
    k_node_scores<<<NB_SCORE, 256>>>(emb);

    // ---- layer 0 (emb -> g_h), fused next-layer scores ----
    k_layer<0, 1><<<NB_NODE16, 256>>>(emb, emb, h_buf, s0, d0);

    // ---- layer 1 (g_h -> out), final: store ex/dinv, loss_a ----
    k_layer<1, 0><<<NB_NODE16, 256>>>(h_buf, emb, out, s1, d1);

    // ---- loss_b ----
    k_loss<<<NB_NODE16, 256>>>(out);
    k_finalize<<<1, 1>>>(out);
}

// round 7
// speedup vs baseline: 1.3239x; 1.0595x over previous
#include <cuda_runtime.h>
#include <cuda_bf16.h>

#define N_NODES 50000
#define E_EDGES 800000
#define H_DIM   64
#define GAMMA   0.2f

#define SCAN_CHUNK 1024
#define SCAN_NBLK  ((N_NODES + SCAN_CHUNK - 1) / SCAN_CHUNK)   // 49

// ---------------- device scratch (static, allocation-free) ----------------
__device__ float    g_vsrc[H_DIM];
__device__ float    g_vdst[H_DIM];
__device__ float    g_s0[N_NODES];
__device__ float    g_d0[N_NODES];
__device__ float    g_s1[N_NODES];
__device__ float    g_d1[N_NODES];
__device__ unsigned g_cnt[N_NODES];
__device__ unsigned g_rowptr[N_NODES + 1];
__device__ unsigned g_cursor[N_NODES];
__device__ unsigned g_blksum[SCAN_NBLK];
__device__ int      g_srcs[E_EDGES];      // src id, grouped by dst (CSR)
__device__ float    g_ex[E_EDGES];        // last-layer exp(e), CSR order
__device__ float    g_dinv[N_NODES];      // last-layer 1/denom
__device__ float    g_h[N_NODES * H_DIM];
__device__ float    g_sumA;
__device__ float    g_sumB;

// ---------------- kernels ----------------

// fused: block 0 computes v_src = W^T a_src, v_dst = W^T a_dst + zeros sums;
// all blocks histogram dst into g_cnt (g_cnt pre-zeroed by memset node).
__global__ void k_prep_hist(const float* __restrict__ W, const float* __restrict__ attn,
                            const int* __restrict__ dst) {
    int i = blockIdx.x * blockDim.x + threadIdx.x;
    if (blockIdx.x == 0 && threadIdx.x < 128) {
        int t = threadIdx.x;
        if (t == 0) { g_sumA = 0.f; g_sumB = 0.f; }
        if (t < H_DIM) {
            float acc = 0.f;
            #pragma unroll 8
            for (int r = 0; r < H_DIM; r++) acc += attn[r] * W[r * H_DIM + t];
            g_vsrc[t] = acc;
        } else {
            int c = t - H_DIM;
            float acc = 0.f;
            #pragma unroll 8
            for (int r = 0; r < H_DIM; r++) acc += attn[H_DIM + r] * W[r * H_DIM + c];
            g_vdst[c] = acc;
        }
    }
    if (i < E_EDGES) atomicAdd(&g_cnt[dst[i]], 1u);
}

// per-block exclusive scan of g_cnt -> g_rowptr (block-local), totals -> g_blksum
__global__ void k_scan1() {
    __shared__ unsigned warp_sums[32];
    int t = threadIdx.x, lane = t & 31, wid = t >> 5;
    int idx = blockIdx.x * SCAN_CHUNK + t;

    unsigned orig = (idx < N_NODES) ? g_cnt[idx] : 0u;
    unsigned v = orig;
    #pragma unroll
    for (int o = 1; o < 32; o <<= 1) {
        unsigned u = __shfl_up_sync(0xffffffffu, v, o);
        if (lane >= o) v += u;
    }
    if (lane == 31) warp_sums[wid] = v;
    __syncthreads();
    if (wid == 0) {
        unsigned w = warp_sums[lane];
        #pragma unroll
        for (int o = 1; o < 32; o <<= 1) {
            unsigned u = __shfl_up_sync(0xffffffffu, w, o);
            if (lane >= o) w += u;
        }
        warp_sums[lane] = w;
    }
    __syncthreads();
    unsigned pre = (wid > 0) ? warp_sums[wid - 1] : 0u;
    if (idx < N_NODES) g_rowptr[idx] = pre + v - orig;   // block-local exclusive
    if (t == SCAN_CHUNK - 1) g_blksum[blockIdx.x] = warp_sums[31];
}

// fused scan2+3: each 256-thread block covers nodes inside ONE scan chunk
// (256 | 1024), so it needs a single offset = sum of blksum below its chunk.
__global__ void k_scan23() {
    __shared__ unsigned s_off;
    int chunk = (blockIdx.x * 256) / SCAN_CHUNK;

    if (threadIdx.x < 32) {                 // warp 0: offset for this block
        unsigned v = 0;
        for (int k = threadIdx.x; k < chunk; k += 32) v += g_blksum[k];
        #pragma unroll
        for (int o = 16; o; o >>= 1) v += __shfl_xor_sync(0xffffffffu, v, o);
        if (threadIdx.x == 0) s_off = v;
    } else if (blockIdx.x == 0 && threadIdx.x < 64) {   // warp 1 of block 0: total
        int lane = threadIdx.x - 32;
        unsigned v = 0;
        for (int k = lane; k < SCAN_NBLK; k += 32) v += g_blksum[k];
        #pragma unroll
        for (int o = 16; o; o >>= 1) v += __shfl_xor_sync(0xffffffffu, v, o);
        if (lane == 0) g_rowptr[N_NODES] = v;
    }
    __syncthreads();
    int i = blockIdx.x * 256 + threadIdx.x;
    if (i < N_NODES) {
        unsigned r = g_rowptr[i] + s_off;
        g_rowptr[i] = r;
        g_cursor[i] = r;
    }
}

// fused: scatter edges into CSR + compute layer-0 node scores (independent work).
// grid = E/256 = 3125 blocks; score part active for i < N*8 = 400000 (warp-aligned).
__global__ void k_scatter_scores(const int* __restrict__ src, const int* __restrict__ dst,
                                 const float* __restrict__ emb) {
    int i = blockIdx.x * blockDim.x + threadIdx.x;
    if (i < E_EDGES) {
        unsigned pos = atomicAdd(&g_cursor[dst[i]], 1u);
        g_srcs[pos] = src[i];
    }
    if (i < N_NODES * 8) {
        int node = i >> 3;
        int part = i & 7;
        const float4* hp = (const float4*)(emb + (size_t)node * H_DIM);
        const float4* vs = (const float4*)g_vsrc;
        const float4* vd = (const float4*)g_vdst;
        float4 a = hp[part * 2], b = hp[part * 2 + 1];
        float4 v0 = vs[part * 2], v1 = vs[part * 2 + 1];
        float4 w0 = vd[part * 2], w1 = vd[part * 2 + 1];

        float s = a.x * v0.x + a.y * v0.y + a.z * v0.z + a.w * v0.w
                + b.x * v1.x + b.y * v1.y + b.z * v1.z + b.w * v1.w;
        float d = a.x * w0.x + a.y * w0.y + a.z * w0.z + a.w * w0.w
                + b.x * w1.x + b.y * w1.y + b.z * w1.z + b.w * w1.w;
        #pragma unroll
        for (int off = 4; off; off >>= 1) {
            s += __shfl_xor_sync(0xffffffffu, s, off);
            d += __shfl_xor_sync(0xffffffffu, d, off);
        }
        if (part == 0) { g_s0[node] = s; g_d0[node] = d; }
    }
}

// fused per-node layer, single pass (softmax shift-invariance: no segment max).
// 16 threads/node; edge loop manually unrolled x4 for MLP.
template <int FINAL, int WSCORES>
__global__ void k_layer(const float* __restrict__ h_in,
                        const float* __restrict__ emb,
                        float* __restrict__ h_out,
                        const float* __restrict__ s_in,
                        const float* __restrict__ d_in) {
    int gid  = blockIdx.x * blockDim.x + threadIdx.x;   // exact grid: N*16
    int node = gid >> 4;
    int part = gid & 15;

    unsigned beg = g_rowptr[node], end = g_rowptr[node + 1];
    float dloc = d_in[node];

    float4 acc = make_float4(0.f, 0.f, 0.f, 0.f);
    float den = 0.f;
    unsigned j = beg;
    for (; j + 4 <= end; j += 4) {
        int s0 = g_srcs[j], s1 = g_srcs[j + 1], s2 = g_srcs[j + 2], s3 = g_srcs[j + 3];
        float e0 = s_in[s0] + dloc, e1 = s_in[s1] + dloc,
              e2 = s_in[s2] + dloc, e3 = s_in[s3] + dloc;
        e0 = e0 > 0.f ? e0 : GAMMA * e0;  e1 = e1 > 0.f ? e1 : GAMMA * e1;
        e2 = e2 > 0.f ? e2 : GAMMA * e2;  e3 = e3 > 0.f ? e3 : GAMMA * e3;
        float x0 = __expf(e0), x1 = __expf(e1), x2 = __expf(e2), x3 = __expf(e3);
        float4 h0 = *(const float4*)(h_in + (size_t)s0 * H_DIM + part * 4);
        float4 h1 = *(const float4*)(h_in + (size_t)s1 * H_DIM + part * 4);
        float4 h2 = *(const float4*)(h_in + (size_t)s2 * H_DIM + part * 4);
        float4 h3 = *(const float4*)(h_in + (size_t)s3 * H_DIM + part * 4);
        den += (x0 + x1) + (x2 + x3);
        acc.x += x0 * h0.x + x1 * h1.x + x2 * h2.x + x3 * h3.x;
        acc.y += x0 * h0.y + x1 * h1.y + x2 * h2.y + x3 * h3.y;
        acc.z += x0 * h0.z + x1 * h1.z + x2 * h2.z + x3 * h3.z;
        acc.w += x0 * h0.w + x1 * h1.w + x2 * h2.w + x3 * h3.w;
        if (FINAL && part == 0) {
            g_ex[j] = x0; g_ex[j + 1] = x1; g_ex[j + 2] = x2; g_ex[j + 3] = x3;
        }
    }
    for (; j < end; j++) {
        int sj = g_srcs[j];
        float e = s_in[sj] + dloc;
        e = e > 0.f ? e : GAMMA * e;
        float ex = __expf(e);
        den += ex;
        float4 hv = *(const float4*)(h_in + (size_t)sj * H_DIM + part * 4);
        acc.x += ex * hv.x; acc.y += ex * hv.y;
        acc.z += ex * hv.z; acc.w += ex * hv.w;
        if (FINAL && part == 0) g_ex[j] = ex;
    }
    float inv = 1.f / fmaxf(den, 1e-16f);
    float4 eb = *(const float4*)(emb + (size_t)node * H_DIM + part * 4);
    float4 hv = make_float4(0.5f * (eb.x + acc.x * inv), 0.5f * (eb.y + acc.y * inv),
                            0.5f * (eb.z + acc.z * inv), 0.5f * (eb.w + acc.w * inv));
    *(float4*)(h_out + (size_t)node * H_DIM + part * 4) = hv;

    // ----- post-loop: all 32 lanes reconverged; full-mask shuffles safe -----
    if (WSCORES) {
        float4 v0 = ((const float4*)g_vsrc)[part];
        float4 w0 = ((const float4*)g_vdst)[part];
        float sp = hv.x * v0.x + hv.y * v0.y + hv.z * v0.z + hv.w * v0.w;
        float dp = hv.x * w0.x + hv.y * w0.y + hv.z * w0.z + hv.w * w0.w;
        #pragma unroll
        for (int off = 8; off; off >>= 1) {
            sp += __shfl_xor_sync(0xffffffffu, sp, off);
            dp += __shfl_xor_sync(0xffffffffu, dp, off);
        }
        if (part == 0) { g_s1[node] = sp; g_d1[node] = dp; }
    }

    if (FINAL) {
        if (part == 0) g_dinv[node] = inv;
        float dx = hv.x - eb.x, dy = hv.y - eb.y, dz = hv.z - eb.z, dw = hv.w - eb.w;
        float sq = dx * dx + dy * dy + dz * dz + dw * dw;
        #pragma unroll
        for (int off = 16; off; off >>= 1) sq += __shfl_xor_sync(0xffffffffu, sq, off);
        __shared__ float sm[8];
        if ((threadIdx.x & 31) == 0) sm[threadIdx.x >> 5] = sq;
        __syncthreads();
        if (threadIdx.x < 8) {
            float v = sm[threadIdx.x];
            #pragma unroll
            for (int o = 4; o; o >>= 1) v += __shfl_xor_sync(0xffu, v, o);
            if (threadIdx.x == 0) atomicAdd(&g_sumA, v);
        }
    }
}

// loss_b, lane-per-part (coalesced), unrolled x2. In-loop shuffles use the
// 16-lane group mask (uniform trip count within a group; divergent across groups).
__global__ void k_loss(const float* __restrict__ h) {
    int gid  = blockIdx.x * blockDim.x + threadIdx.x;   // exact grid: N*16
    int node = gid >> 4;
    int part = gid & 15;
    unsigned gmask = 0xFFFFu << (threadIdx.x & 16);

    unsigned beg = g_rowptr[node], end = g_rowptr[node + 1];
    float4 hd = *(const float4*)(h + (size_t)node * H_DIM + part * 4);
    float dinv = g_dinv[node];

    float sum = 0.f;
    unsigned j = beg;
    for (; j + 2 <= end; j += 2) {
        int s0 = g_srcs[j], s1 = g_srcs[j + 1];
        float4 a0 = *(const float4*)(h + (size_t)s0 * H_DIM + part * 4);
        float4 a1 = *(const float4*)(h + (size_t)s1 * H_DIM + part * 4);
        float q0 = (hd.x - a0.x) * (hd.x - a0.x) + (hd.y - a0.y) * (hd.y - a0.y)
                 + (hd.z - a0.z) * (hd.z - a0.z) + (hd.w - a0.w) * (hd.w - a0.w);
        float q1 = (hd.x - a1.x) * (hd.x - a1.x) + (hd.y - a1.y) * (hd.y - a1.y)
                 + (hd.z - a1.z) * (hd.z - a1.z) + (hd.w - a1.w) * (hd.w - a1.w);
        #pragma unroll
        for (int off = 8; off; off >>= 1) {
            q0 += __shfl_xor_sync(gmask, q0, off);
            q1 += __shfl_xor_sync(gmask, q1, off);
        }
        sum += g_ex[j] * sqrtf(q0 + 1e-12f) + g_ex[j + 1] * sqrtf(q1 + 1e-12f);
    }
    if (j < end) {
        int sj = g_srcs[j];
        float4 a = *(const float4*)(h + (size_t)sj * H_DIM + part * 4);
        float q = (hd.x - a.x) * (hd.x - a.x) + (hd.y - a.y) * (hd.y - a.y)
                + (hd.z - a.z) * (hd.z - a.z) + (hd.w - a.w) * (hd.w - a.w);
        #pragma unroll
        for (int off = 8; off; off >>= 1) q += __shfl_xor_sync(gmask, q, off);
        sum += g_ex[j] * sqrtf(q + 1e-12f);
    }
    sum = (part == 0) ? sum * dinv : 0.f;   // one copy per node
    // converged below loop: full-warp reduction safe
    #pragma unroll
    for (int off = 16; off; off >>= 1) sum += __shfl_xor_sync(0xffffffffu, sum, off);
    __shared__ float sm[8];
    if ((threadIdx.x & 31) == 0) sm[threadIdx.x >> 5] = sum;
    __syncthreads();
    if (threadIdx.x < 8) {
        float v = sm[threadIdx.x];
        #pragma unroll
        for (int o = 4; o; o >>= 1) v += __shfl_xor_sync(0xffu, v, o);
        if (threadIdx.x == 0) atomicAdd(&g_sumB, v);
    }
}

__global__ void k_finalize(float* __restrict__ out) {
    out[N_NODES * H_DIM] = 0.5f * (g_sumA + g_sumB) / (float)N_NODES;
}

// ---------------- launch ----------------
extern "C" void kernel_launch(void* const* d_in, const int* in_sizes, int n_in,
                              void* d_out, int out_size) {
    const float* emb  = (const float*)d_in[0];   // [N, H]
    const float* W    = (const float*)d_in[1];   // [H, H]
    const float* attn = (const float*)d_in[2];   // [1, 2H]
    const int*   src  = (const int*)d_in[3];     // [E]
    const int*   dst  = (const int*)d_in[4];     // [E]
    float* out = (float*)d_out;                  // [N*H + 1]

    float *h_buf = nullptr, *cnt_ptr = nullptr;
    float *s0 = nullptr, *d0 = nullptr, *s1 = nullptr, *d1 = nullptr;
    cudaGetSymbolAddress((void**)&h_buf, g_h);
    cudaGetSymbolAddress((void**)&cnt_ptr, g_cnt);
    cudaGetSymbolAddress((void**)&s0, g_s0);
    cudaGetSymbolAddress((void**)&d0, g_d0);
    cudaGetSymbolAddress((void**)&s1, g_s1);
    cudaGetSymbolAddress((void**)&d1, g_d1);

    const int NB_NODE1  = (N_NODES + 255) / 256;       // 196
    const int NB_EDGE1  = (E_EDGES + 255) / 256;       // 3125
    const int NB_NODE16 = (N_NODES * 16) / 256;        // 3125 (exact)

    // ---- CSR build + prep, fused/hierarchical ----
    cudaMemsetAsync(cnt_ptr, 0, N_NODES * sizeof(unsigned));
    k_prep_hist<<<NB_EDGE1, 256>>>(W, attn, dst);
    k_scan1<<<SCAN_NBLK, SCAN_CHUNK>>>();
    k_scan23<<<NB_NODE1, 256>>>();
    k_scatter_scores<<<NB_EDGE1, 256>>>(src, dst, emb);

    // ---- layer 0 (emb -> g_h), fused next-layer scores ----
    k_layer<0, 1><<<NB_NODE16, 256>>>(emb, emb, h_buf, s0, d0);

    // ---- layer 1 (g_h -> out), final: store ex/dinv, loss_a ----
    k_layer<1, 0><<<NB_NODE16, 256>>>(h_buf, emb, out, s1, d1);

    // ---- loss_b ----
    k_loss<<<NB_NODE16, 256>>>(out);
    k_finalize<<<1, 1>>>(out);
}

// round 8
// speedup vs baseline: 1.3383x; 1.0109x over previous
#include <cuda_runtime.h>
#include <cuda_bf16.h>

#define N_NODES 50000
#define E_EDGES 800000
#define H_DIM   64
#define GAMMA   0.2f

#define SCAN_CHUNK 1024
#define SCAN_NBLK  ((N_NODES + SCAN_CHUNK - 1) / SCAN_CHUNK)   // 49
#define E_QUARTER  (E_EDGES / 4)                               // 200000, exact

// ---------------- device scratch (static, allocation-free) ----------------
__device__ float    g_vsrc[H_DIM];
__device__ float    g_vdst[H_DIM];
__device__ float    g_s0[N_NODES];
__device__ float    g_d0[N_NODES];
__device__ float    g_s1[N_NODES];
__device__ float    g_d1[N_NODES];
__device__ unsigned g_cnt[N_NODES];
__device__ unsigned g_rowptr[N_NODES + 1];
__device__ unsigned g_cursor[N_NODES];
__device__ unsigned g_blksum[SCAN_NBLK];
__device__ int      g_srcs[E_EDGES];      // src id, grouped by dst (CSR)
__device__ float    g_ex[E_EDGES];        // last-layer exp(e), CSR order
__device__ float    g_dinv[N_NODES];      // last-layer 1/denom
__device__ float    g_h[N_NODES * H_DIM];
__device__ float    g_sumA;
__device__ float    g_sumB;

// ---------------- kernels ----------------

// fused: block 0 computes v_src = W^T a_src, v_dst = W^T a_dst + zeros sums;
// all blocks histogram dst (x4 per thread, int4 reads -> 4 independent REDs).
__global__ void k_prep_hist(const float* __restrict__ W, const float* __restrict__ attn,
                            const int* __restrict__ dst) {
    int i = blockIdx.x * blockDim.x + threadIdx.x;
    if (blockIdx.x == 0 && threadIdx.x < 128) {
        int t = threadIdx.x;
        if (t == 0) { g_sumA = 0.f; g_sumB = 0.f; }
        if (t < H_DIM) {
            float acc = 0.f;
            #pragma unroll 8
            for (int r = 0; r < H_DIM; r++) acc += attn[r] * W[r * H_DIM + t];
            g_vsrc[t] = acc;
        } else {
            int c = t - H_DIM;
            float acc = 0.f;
            #pragma unroll 8
            for (int r = 0; r < H_DIM; r++) acc += attn[H_DIM + r] * W[r * H_DIM + c];
            g_vdst[c] = acc;
        }
    }
    if (i < E_QUARTER) {
        int4 d = ((const int4*)dst)[i];
        atomicAdd(&g_cnt[d.x], 1u);
        atomicAdd(&g_cnt[d.y], 1u);
        atomicAdd(&g_cnt[d.z], 1u);
        atomicAdd(&g_cnt[d.w], 1u);
    }
}

// per-block exclusive scan of g_cnt -> g_rowptr (block-local), totals -> g_blksum
__global__ void k_scan1() {
    __shared__ unsigned warp_sums[32];
    int t = threadIdx.x, lane = t & 31, wid = t >> 5;
    int idx = blockIdx.x * SCAN_CHUNK + t;

    unsigned orig = (idx < N_NODES) ? g_cnt[idx] : 0u;
    unsigned v = orig;
    #pragma unroll
    for (int o = 1; o < 32; o <<= 1) {
        unsigned u = __shfl_up_sync(0xffffffffu, v, o);
        if (lane >= o) v += u;
    }
    if (lane == 31) warp_sums[wid] = v;
    __syncthreads();
    if (wid == 0) {
        unsigned w = warp_sums[lane];
        #pragma unroll
        for (int o = 1; o < 32; o <<= 1) {
            unsigned u = __shfl_up_sync(0xffffffffu, w, o);
            if (lane >= o) w += u;
        }
        warp_sums[lane] = w;
    }
    __syncthreads();
    unsigned pre = (wid > 0) ? warp_sums[wid - 1] : 0u;
    if (idx < N_NODES) g_rowptr[idx] = pre + v - orig;   // block-local exclusive
    if (t == SCAN_CHUNK - 1) g_blksum[blockIdx.x] = warp_sums[31];
}

// fused scan2+3: each 256-thread block covers nodes inside ONE scan chunk
// (256 | 1024), so it needs a single offset = sum of blksum below its chunk.
__global__ void k_scan23() {
    __shared__ unsigned s_off;
    int chunk = (blockIdx.x * 256) / SCAN_CHUNK;

    if (threadIdx.x < 32) {                 // warp 0: offset for this block
        unsigned v = 0;
        for (int k = threadIdx.x; k < chunk; k += 32) v += g_blksum[k];
        #pragma unroll
        for (int o = 16; o; o >>= 1) v += __shfl_xor_sync(0xffffffffu, v, o);
        if (threadIdx.x == 0) s_off = v;
    } else if (blockIdx.x == 0 && threadIdx.x < 64) {   // warp 1 of block 0: total
        int lane = threadIdx.x - 32;
        unsigned v = 0;
        for (int k = lane; k < SCAN_NBLK; k += 32) v += g_blksum[k];
        #pragma unroll
        for (int o = 16; o; o >>= 1) v += __shfl_xor_sync(0xffffffffu, v, o);
        if (lane == 0) g_rowptr[N_NODES] = v;
    }
    __syncthreads();
    int i = blockIdx.x * 256 + threadIdx.x;
    if (i < N_NODES) {
        unsigned r = g_rowptr[i] + s_off;
        g_rowptr[i] = r;
        g_cursor[i] = r;
    }
}

// fused: scatter edges into CSR (x4 per thread, 4 independent atomic chains)
// + compute layer-0 node scores. grid covers max(N*8, E/4) threads.
__global__ void k_scatter_scores(const int* __restrict__ src, const int* __restrict__ dst,
                                 const float* __restrict__ emb) {
    int i = blockIdx.x * blockDim.x + threadIdx.x;
    if (i < E_QUARTER) {
        int4 s = ((const int4*)src)[i];
        int4 d = ((const int4*)dst)[i];
        unsigned p0 = atomicAdd(&g_cursor[d.x], 1u);
        unsigned p1 = atomicAdd(&g_cursor[d.y], 1u);
        unsigned p2 = atomicAdd(&g_cursor[d.z], 1u);
        unsigned p3 = atomicAdd(&g_cursor[d.w], 1u);
        g_srcs[p0] = s.x;
        g_srcs[p1] = s.y;
        g_srcs[p2] = s.z;
        g_srcs[p3] = s.w;
    }
    if (i < N_NODES * 8) {
        int node = i >> 3;
        int part = i & 7;
        const float4* hp = (const float4*)(emb + (size_t)node * H_DIM);
        const float4* vs = (const float4*)g_vsrc;
        const float4* vd = (const float4*)g_vdst;
        float4 a = hp[part * 2], b = hp[part * 2 + 1];
        float4 v0 = vs[part * 2], v1 = vs[part * 2 + 1];
        float4 w0 = vd[part * 2], w1 = vd[part * 2 + 1];

        float s = a.x * v0.x + a.y * v0.y + a.z * v0.z + a.w * v0.w
                + b.x * v1.x + b.y * v1.y + b.z * v1.z + b.w * v1.w;
        float d = a.x * w0.x + a.y * w0.y + a.z * w0.z + a.w * w0.w
                + b.x * w1.x + b.y * w1.y + b.z * w1.z + b.w * w1.w;
        #pragma unroll
        for (int off = 4; off; off >>= 1) {
            s += __shfl_xor_sync(0xffffffffu, s, off);
            d += __shfl_xor_sync(0xffffffffu, d, off);
        }
        if (part == 0) { g_s0[node] = s; g_d0[node] = d; }
    }
}

// fused per-node layer, single pass (softmax shift-invariance: no segment max).
// 16 threads/node; edge loop manually unrolled x4 for MLP.
template <int FINAL, int WSCORES>
__global__ void k_layer(const float* __restrict__ h_in,
                        const float* __restrict__ emb,
                        float* __restrict__ h_out,
                        const float* __restrict__ s_in,
                        const float* __restrict__ d_in) {
    int gid  = blockIdx.x * blockDim.x + threadIdx.x;   // exact grid: N*16
    int node = gid >> 4;
    int part = gid & 15;

    unsigned beg = g_rowptr[node], end = g_rowptr[node + 1];
    float dloc = d_in[node];

    float4 acc = make_float4(0.f, 0.f, 0.f, 0.f);
    float den = 0.f;
    unsigned j = beg;
    for (; j + 4 <= end; j += 4) {
        int s0 = g_srcs[j], s1 = g_srcs[j + 1], s2 = g_srcs[j + 2], s3 = g_srcs[j + 3];
        float e0 = s_in[s0] + dloc, e1 = s_in[s1] + dloc,
              e2 = s_in[s2] + dloc, e3 = s_in[s3] + dloc;
        e0 = e0 > 0.f ? e0 : GAMMA * e0;  e1 = e1 > 0.f ? e1 : GAMMA * e1;
        e2 = e2 > 0.f ? e2 : GAMMA * e2;  e3 = e3 > 0.f ? e3 : GAMMA * e3;
        float x0 = __expf(e0), x1 = __expf(e1), x2 = __expf(e2), x3 = __expf(e3);
        float4 h0 = *(const float4*)(h_in + (size_t)s0 * H_DIM + part * 4);
        float4 h1 = *(const float4*)(h_in + (size_t)s1 * H_DIM + part * 4);
        float4 h2 = *(const float4*)(h_in + (size_t)s2 * H_DIM + part * 4);
        float4 h3 = *(const float4*)(h_in + (size_t)s3 * H_DIM + part * 4);
        den += (x0 + x1) + (x2 + x3);
        acc.x += x0 * h0.x + x1 * h1.x + x2 * h2.x + x3 * h3.x;
        acc.y += x0 * h0.y + x1 * h1.y + x2 * h2.y + x3 * h3.y;
        acc.z += x0 * h0.z + x1 * h1.z + x2 * h2.z + x3 * h3.z;
        acc.w += x0 * h0.w + x1 * h1.w + x2 * h2.w + x3 * h3.w;
        if (FINAL && part == 0) {
            g_ex[j] = x0; g_ex[j + 1] = x1; g_ex[j + 2] = x2; g_ex[j + 3] = x3;
        }
    }
    for (; j < end; j++) {
        int sj = g_srcs[j];
        float e = s_in[sj] + dloc;
        e = e > 0.f ? e : GAMMA * e;
        float ex = __expf(e);
        den += ex;
        float4 hv = *(const float4*)(h_in + (size_t)sj * H_DIM + part * 4);
        acc.x += ex * hv.x; acc.y += ex * hv.y;
        acc.z += ex * hv.z; acc.w += ex * hv.w;
        if (FINAL && part == 0) g_ex[j] = ex;
    }
    float inv = 1.f / fmaxf(den, 1e-16f);
    float4 eb = *(const float4*)(emb + (size_t)node * H_DIM + part * 4);
    float4 hv = make_float4(0.5f * (eb.x + acc.x * inv), 0.5f * (eb.y + acc.y * inv),
                            0.5f * (eb.z + acc.z * inv), 0.5f * (eb.w + acc.w * inv));
    *(float4*)(h_out + (size_t)node * H_DIM + part * 4) = hv;

    // ----- post-loop: all 32 lanes reconverged; full-mask shuffles safe -----
    if (WSCORES) {
        float4 v0 = ((const float4*)g_vsrc)[part];
        float4 w0 = ((const float4*)g_vdst)[part];
        float sp = hv.x * v0.x + hv.y * v0.y + hv.z * v0.z + hv.w * v0.w;
        float dp = hv.x * w0.x + hv.y * w0.y + hv.z * w0.z + hv.w * w0.w;
        #pragma unroll
        for (int off = 8; off; off >>= 1) {
            sp += __shfl_xor_sync(0xffffffffu, sp, off);
            dp += __shfl_xor_sync(0xffffffffu, dp, off);
        }
        if (part == 0) { g_s1[node] = sp; g_d1[node] = dp; }
    }

    if (FINAL) {
        if (part == 0) g_dinv[node] = inv;
        float dx = hv.x - eb.x, dy = hv.y - eb.y, dz = hv.z - eb.z, dw = hv.w - eb.w;
        float sq = dx * dx + dy * dy + dz * dz + dw * dw;
        #pragma unroll
        for (int off = 16; off; off >>= 1) sq += __shfl_xor_sync(0xffffffffu, sq, off);
        __shared__ float sm[8];
        if ((threadIdx.x & 31) == 0) sm[threadIdx.x >> 5] = sq;
        __syncthreads();
        if (threadIdx.x < 8) {
            float v = sm[threadIdx.x];
            #pragma unroll
            for (int o = 4; o; o >>= 1) v += __shfl_xor_sync(0xffu, v, o);
            if (threadIdx.x == 0) atomicAdd(&g_sumA, v);
        }
    }
}

// loss_b, lane-per-part (coalesced), unrolled x2. In-loop shuffles use the
// 16-lane group mask (uniform trip count within a group; divergent across groups).
__global__ void k_loss(const float* __restrict__ h) {
    int gid  = blockIdx.x * blockDim.x + threadIdx.x;   // exact grid: N*16
    int node = gid >> 4;
    int part = gid & 15;
    unsigned gmask = 0xFFFFu << (threadIdx.x & 16);

    unsigned beg = g_rowptr[node], end = g_rowptr[node + 1];
    float4 hd = *(const float4*)(h + (size_t)node * H_DIM + part * 4);
    float dinv = g_dinv[node];

    float sum = 0.f;
    unsigned j = beg;
    for (; j + 2 <= end; j += 2) {
        int s0 = g_srcs[j], s1 = g_srcs[j + 1];
        float4 a0 = *(const float4*)(h + (size_t)s0 * H_DIM + part * 4);
        float4 a1 = *(const float4*)(h + (size_t)s1 * H_DIM + part * 4);
        float q0 = (hd.x - a0.x) * (hd.x - a0.x) + (hd.y - a0.y) * (hd.y - a0.y)
                 + (hd.z - a0.z) * (hd.z - a0.z) + (hd.w - a0.w) * (hd.w - a0.w);
        float q1 = (hd.x - a1.x) * (hd.x - a1.x) + (hd.y - a1.y) * (hd.y - a1.y)
                 + (hd.z - a1.z) * (hd.z - a1.z) + (hd.w - a1.w) * (hd.w - a1.w);
        #pragma unroll
        for (int off = 8; off; off >>= 1) {
            q0 += __shfl_xor_sync(gmask, q0, off);
            q1 += __shfl_xor_sync(gmask, q1, off);
        }
        sum += g_ex[j] * sqrtf(q0 + 1e-12f) + g_ex[j + 1] * sqrtf(q1 + 1e-12f);
    }
    if (j < end) {
        int sj = g_srcs[j];
        float4 a = *(const float4*)(h + (size_t)sj * H_DIM + part * 4);
        float q = (hd.x - a.x) * (hd.x - a.x) + (hd.y - a.y) * (hd.y - a.y)
                + (hd.z - a.z) * (hd.z - a.z) + (hd.w - a.w) * (hd.w - a.w);
        #pragma unroll
        for (int off = 8; off; off >>= 1) q += __shfl_xor_sync(gmask, q, off);
        sum += g_ex[j] * sqrtf(q + 1e-12f);
    }
    sum = (part == 0) ? sum * dinv : 0.f;   // one copy per node
    // converged below loop: full-warp reduction safe
    #pragma unroll
    for (int off = 16; off; off >>= 1) sum += __shfl_xor_sync(0xffffffffu, sum, off);
    __shared__ float sm[8];
    if ((threadIdx.x & 31) == 0) sm[threadIdx.x >> 5] = sum;
    __syncthreads();
    if (threadIdx.x < 8) {
        float v = sm[threadIdx.x];
        #pragma unroll
        for (int o = 4; o; o >>= 1) v += __shfl_xor_sync(0xffu, v, o);
        if (threadIdx.x == 0) atomicAdd(&g_sumB, v);
    }
}

__global__ void k_finalize(float* __restrict__ out) {
    out[N_NODES * H_DIM] = 0.5f * (g_sumA + g_sumB) / (float)N_NODES;
}

// ---------------- launch ----------------
extern "C" void kernel_launch(void* const* d_in, const int* in_sizes, int n_in,
                              void* d_out, int out_size) {
    const float* emb  = (const float*)d_in[0];   // [N, H]
    const float* W    = (const float*)d_in[1];   // [H, H]
    const float* attn = (const float*)d_in[2];   // [1, 2H]
    const int*   src  = (const int*)d_in[3];     // [E]
    const int*   dst  = (const int*)d_in[4];     // [E]
    float* out = (float*)d_out;                  // [N*H + 1]

    float *h_buf = nullptr, *cnt_ptr = nullptr;
    float *s0 = nullptr, *d0 = nullptr, *s1 = nullptr, *d1 = nullptr;
    cudaGetSymbolAddress((void**)&h_buf, g_h);
    cudaGetSymbolAddress((void**)&cnt_ptr, g_cnt);
    cudaGetSymbolAddress((void**)&s0, g_s0);
    cudaGetSymbolAddress((void**)&d0, g_d0);
    cudaGetSymbolAddress((void**)&s1, g_s1);
    cudaGetSymbolAddress((void**)&d1, g_d1);

    const int NB_NODE1   = (N_NODES + 255) / 256;      // 196
    const int NB_EQ      = (E_QUARTER + 255) / 256;    // 782
    const int NB_SCATTER = (N_NODES * 8 + 255) / 256;  // 1563 (covers E/4 too)
    const int NB_NODE16  = (N_NODES * 16) / 256;       // 3125 (exact)

    // ---- CSR build + prep, fused/hierarchical ----
    cudaMemsetAsync(cnt_ptr, 0, N_NODES * sizeof(unsigned));
    k_prep_hist<<<NB_EQ, 256>>>(W, attn, dst);
    k_scan1<<<SCAN_NBLK, SCAN_CHUNK>>>();
    k_scan23<<<NB_NODE1, 256>>>();
    k_scatter_scores<<<NB_SCATTER, 256>>>(src, dst, emb);

    // ---- layer 0 (emb -> g_h), fused next-layer scores ----
    k_layer<0, 1><<<NB_NODE16, 256>>>(emb, emb, h_buf, s0, d0);

    // ---- layer 1 (g_h -> out), final: store ex/dinv, loss_a ----
    k_layer<1, 0><<<NB_NODE16, 256>>>(h_buf, emb, out, s1, d1);

    // ---- loss_b ----
    k_loss<<<NB_NODE16, 256>>>(out);
    k_finalize<<<1, 1>>>(out);
}